// round 4
// baseline (speedup 1.0000x reference)
#include <cuda_runtime.h>
#include <cuda_bf16.h>
#include <cstdint>

// RNN_438086664357: h_{t+1} = tanh(W [h_t ; x_t] + b)
// Round 4: HMMA bf16 3-product split; 8 warps/CTA (k16-split), independent
// accumulators per product, smem reduction epilogue.

#define TSTEPS 256
#define BATCH  256
#define DH     1024
#define DIN    1024
#define KTOT   2048
#define BM     32
#define BN     64
#define KC     64
#define NCH    (KTOT / KC)     // 32
#define S      4

#define OFF_AHI 0
#define OFF_ALO 4096
#define OFF_WHI 8192
#define OFF_WLO 16384
#define STG     24576
#define SMEM_BYTES (S * STG)   // 98304

typedef unsigned int u32;

__device__ __nv_bfloat16 g_xhi[(size_t)TSTEPS * BATCH * DIN];
__device__ __nv_bfloat16 g_xlo[(size_t)TSTEPS * BATCH * DIN];
__device__ __nv_bfloat16 g_whi[(size_t)DH * KTOT];
__device__ __nv_bfloat16 g_wlo[(size_t)DH * KTOT];
__device__ __nv_bfloat16 g_hhi[2 * (size_t)BATCH * DH];
__device__ __nv_bfloat16 g_hlo[2 * (size_t)BATCH * DH];

__device__ __forceinline__ u32 s2u(const void* p) {
    u32 a;
    asm("{ .reg .u64 t; cvta.to.shared.u64 t, %1; cvt.u32.u64 %0, t; }"
        : "=r"(a) : "l"(p));
    return a;
}

#define CP16(sm, gp) asm volatile("cp.async.cg.shared.global [%0], [%1], 16;" :: "r"(sm), "l"(gp))
#define CP_COMMIT()  asm volatile("cp.async.commit_group;" ::: "memory")

__device__ __forceinline__ void ldsm4(u32 a, u32& r0, u32& r1, u32& r2, u32& r3) {
    asm volatile("ldmatrix.sync.aligned.m8n8.x4.shared.b16 {%0,%1,%2,%3}, [%4];"
                 : "=r"(r0), "=r"(r1), "=r"(r2), "=r"(r3) : "r"(a));
}

__device__ __forceinline__ void mma16816(float* c, const u32* a, u32 b0, u32 b1) {
    asm volatile(
        "mma.sync.aligned.m16n8k16.row.col.f32.bf16.bf16.f32 "
        "{%0,%1,%2,%3}, {%4,%5,%6,%7}, {%8,%9}, {%0,%1,%2,%3};"
        : "+f"(c[0]), "+f"(c[1]), "+f"(c[2]), "+f"(c[3])
        : "r"(a[0]), "r"(a[1]), "r"(a[2]), "r"(a[3]), "r"(b0), "r"(b1));
}

// ---- setup ----
__global__ void split_w(const float* __restrict__ W) {
    int i = blockIdx.x * blockDim.x + threadIdx.x;
    float v = W[i];
    __nv_bfloat16 h = __float2bfloat16(v);
    g_whi[i] = h;
    g_wlo[i] = __float2bfloat16(v - __bfloat162float(h));
}

__global__ void split_x(const float* __restrict__ X) {
    size_t i = (size_t)blockIdx.x * blockDim.x + threadIdx.x;
    float v = X[i];
    __nv_bfloat16 h = __float2bfloat16(v);
    g_xhi[i] = h;
    g_xlo[i] = __float2bfloat16(v - __bfloat162float(h));
}

__global__ void init_h(float* __restrict__ out0) {
    int i = blockIdx.x * blockDim.x + threadIdx.x;
    out0[i] = 0.0f;
    __nv_bfloat16 z = __float2bfloat16(0.0f);
    g_hhi[i] = z;  g_hlo[i] = z;
    g_hhi[BATCH * DH + i] = z;  g_hlo[BATCH * DH + i] = z;
}

// ---- per-step GEMM + tanh + split ----
__global__ void __launch_bounds__(256, 1)
rnn_step(const float* __restrict__ bias, float* __restrict__ outNext,
         int t, int parity)
{
    extern __shared__ char smem[];
    const u32 sb = s2u(smem);
    const int tid  = threadIdx.x;
    const int wid  = tid >> 5, lane = tid & 31;
    const int wk   = wid >> 2;       // k16-slice group (0: j=0,1 / 1: j=2,3)
    const int wq   = wid & 3;        // output tile within CTA
    const int wm   = wq & 1;         // m16 tile (2)
    const int wn   = wq >> 1;        // n32 half (2)
    const int n0   = blockIdx.x * BN;
    const int m0   = blockIdx.y * BM;

    const __nv_bfloat16* Ahi0 = g_hhi + (size_t)parity * BATCH * DH;
    const __nv_bfloat16* Alo0 = g_hlo + (size_t)parity * BATCH * DH;
    const __nv_bfloat16* Xhi0 = g_xhi + (size_t)t * BATCH * DIN;
    const __nv_bfloat16* Xlo0 = g_xlo + (size_t)t * BATCH * DIN;

    // cp.async mapping: 256 threads; r = tid>>3 (0..31), g = tid&7
    const int lr = tid >> 3;
    const int lg = tid & 7;

    auto load_chunk = [&](int cn, int sn) {
        const u32 st = sb + sn * STG;
        const int ko = (cn & 15) * KC;
        const __nv_bfloat16 *pa, *pl;
        if (cn < 16) { pa = Ahi0; pl = Alo0; } else { pa = Xhi0; pl = Xlo0; }
        {   // A: 32 rows x 8 groups -> exactly 1 op/thread per buffer
            u32 so = (u32)(lr * 128 + ((lg ^ (lr & 7)) * 16));
            const size_t go = (size_t)(m0 + lr) * DH + ko + lg * 8;
            CP16(st + OFF_AHI + so, pa + go);
            CP16(st + OFF_ALO + so, pl + go);
        }
        #pragma unroll
        for (int u = 0; u < 2; u++) {   // W: 64 rows -> 2 ops/thread per buffer
            int r = lr + u * 32;
            u32 so = (u32)(r * 128 + ((lg ^ (r & 7)) * 16));
            const size_t go = (size_t)(n0 + r) * KTOT + cn * KC + lg * 8;
            CP16(st + OFF_WHI + so, g_whi + go);
            CP16(st + OFF_WLO + so, g_wlo + go);
        }
        CP_COMMIT();
    };

    // 3 independent accumulator sets (hi*hi, lo*hi, hi*lo), 4 n8-tiles each
    float c0[16], c1[16], c2[16];
    #pragma unroll
    for (int i = 0; i < 16; i++) { c0[i] = 0.f; c1[i] = 0.f; c2[i] = 0.f; }

    const int aRow  = wm * 16 + (lane & 15);
    const int aHi   = (lane >> 4);
    const int bRow0 = wn * 32 + (lane & 7) + ((lane >> 4) & 1) * 8;
    const int bHi   = (lane >> 3) & 1;

    #pragma unroll
    for (int p = 0; p < S - 1; p++) load_chunk(p, p);

    for (int c = 0; c < NCH; c++) {
        const int sc = c & (S - 1);
        if (c < NCH - 2)       asm volatile("cp.async.wait_group 2;" ::: "memory");
        else if (c == NCH - 2) asm volatile("cp.async.wait_group 1;" ::: "memory");
        else                   asm volatile("cp.async.wait_group 0;" ::: "memory");
        __syncthreads();

        const u32 st = sb + sc * STG;
        #pragma unroll
        for (int jj = 0; jj < 2; jj++) {   // this warp's two k16 steps
            const int j = wk * 2 + jj;
            u32 ah[4], al[4], bh[8], bl[8];
            {
                int g = j * 2 + aHi;
                u32 so = (u32)(aRow * 128 + ((g ^ (aRow & 7)) * 16));
                ldsm4(st + OFF_AHI + so, ah[0], ah[1], ah[2], ah[3]);
                ldsm4(st + OFF_ALO + so, al[0], al[1], al[2], al[3]);
            }
            #pragma unroll
            for (int q = 0; q < 2; q++) {
                int r = bRow0 + q * 16;
                int g = j * 2 + bHi;
                u32 so = (u32)(r * 128 + ((g ^ (r & 7)) * 16));
                ldsm4(st + OFF_WHI + so, bh[q*4+0], bh[q*4+1], bh[q*4+2], bh[q*4+3]);
                ldsm4(st + OFF_WLO + so, bl[q*4+0], bl[q*4+1], bl[q*4+2], bl[q*4+3]);
            }
            #pragma unroll
            for (int nt = 0; nt < 4; nt++) {   // 12 independent MMAs
                mma16816(c0 + nt * 4, ah, bh[nt*2+0], bh[nt*2+1]);
                mma16816(c1 + nt * 4, al, bh[nt*2+0], bh[nt*2+1]);
                mma16816(c2 + nt * 4, ah, bl[nt*2+0], bl[nt*2+1]);
            }
        }
        __syncthreads();

        const int cn = c + S - 1;
        if (cn < NCH) load_chunk(cn, cn & (S - 1));
    }

    // fold products
    float s[16];
    #pragma unroll
    for (int i = 0; i < 16; i++) s[i] = c0[i] + c1[i] + c2[i];

    // cross-k-group reduction via smem (stage area is dead now)
    float* red = (float*)smem;           // 4 warps * 32 lanes * 16 = 8KB
    if (wk == 1) {
        #pragma unroll
        for (int i = 0; i < 16; i++) red[(wq * 32 + lane) * 16 + i] = s[i];
    }
    __syncthreads();
    if (wk == 0) {
        #pragma unroll
        for (int i = 0; i < 16; i++) s[i] += red[(wq * 32 + lane) * 16 + i];

        __nv_bfloat16* hh0 = g_hhi + (size_t)(parity ^ 1) * BATCH * DH;
        __nv_bfloat16* hl0 = g_hlo + (size_t)(parity ^ 1) * BATCH * DH;
        const int rL = lane >> 2, cL = (lane & 3) * 2;
        #pragma unroll
        for (int nt = 0; nt < 4; nt++) {
            const int col = n0 + wn * 32 + nt * 8 + cL;
            const float b0 = __ldg(bias + col), b1 = __ldg(bias + col + 1);
            #pragma unroll
            for (int hf = 0; hf < 2; hf++) {
                const int row = m0 + wm * 16 + rL + hf * 8;
                float z0 = s[nt * 4 + hf * 2 + 0] + b0;
                float z1 = s[nt * 4 + hf * 2 + 1] + b1;
                float e0 = __expf(2.0f * z0), e1 = __expf(2.0f * z1);
                float h0 = 1.0f - 2.0f / (e0 + 1.0f);
                float h1 = 1.0f - 2.0f / (e1 + 1.0f);
                *(float2*)(outNext + (size_t)row * DH + col) = make_float2(h0, h1);
                __nv_bfloat16 p0 = __float2bfloat16(h0), p1 = __float2bfloat16(h1);
                __nv_bfloat162 hi2; hi2.x = p0; hi2.y = p1;
                __nv_bfloat162 lo2;
                lo2.x = __float2bfloat16(h0 - __bfloat162float(p0));
                lo2.y = __float2bfloat16(h1 - __bfloat162float(p1));
                *(__nv_bfloat162*)(hh0 + (size_t)row * DH + col) = hi2;
                *(__nv_bfloat162*)(hl0 + (size_t)row * DH + col) = lo2;
            }
        }
    }
}

extern "C" void kernel_launch(void* const* d_in, const int* in_sizes, int n_in,
                              void* d_out, int out_size) {
    const float* seq = (const float*)d_in[0];
    const float* W   = (const float*)d_in[1];
    const float* b   = (const float*)d_in[2];
    float* out = (float*)d_out;
    (void)in_sizes; (void)n_in; (void)out_size;

    cudaFuncSetAttribute(rnn_step, cudaFuncAttributeMaxDynamicSharedMemorySize,
                         SMEM_BYTES);

    const size_t slice = (size_t)BATCH * DH;

    split_w<<<(DH * KTOT) / 256, 256>>>(W);
    split_x<<<(TSTEPS * BATCH * DIN) / 256, 256>>>(seq);
    init_h<<<(BATCH * DH) / 256, 256>>>(out);

    dim3 grid(DH / BN, BATCH / BM);   // (16, 8) = 128 CTAs
    for (int t = 0; t < TSTEPS; t++) {
        rnn_step<<<grid, 256, SMEM_BYTES>>>(b, out + (t + 1) * slice, t, t & 1);
    }
}